// round 3
// baseline (speedup 1.0000x reference)
#include <cuda_runtime.h>
#include <math.h>

#define B 8
#define C 64
#define L 2048
#define BCL (B*C*L)          // 1048576
#define NOUT (4*BCL)
#define NBUF 15

// ---------------- device scratch (no allocation) ----------------
__device__ float g_big[NBUF*BCL];     // 15 x 4MB buffers
__device__ float g_W4s[11*4096*4];    // packed conv weights (float4 per (i,o))
__device__ float g_stat[512];
__device__ float g_lo[56], g_hi[56];
__device__ float g_ortho[1];
__device__ float g_ts[8];
__device__ float g_rows[2048];        // 512 rows x 4 partial sums
__device__ float g_modb[2048];        // [j][s][{1+gamma+se, beta}][64]
__device__ float g_energy[16];
__device__ unsigned g_mm[2];

// buffer slots in g_big
#define S_BUFA 0
#define S_BUFB 1
#define S_DET  2   // 3 buffers
#define S_Y    5
#define S_YIN  6
#define S_ACC  7
#define S_H    8
#define S_EVO  9   // 3 buffers
#define S_CURA 12
#define S_CURB 13
#define S_DMOD 14

// ---------------- helpers ----------------
__device__ __forceinline__ float geluf(float x){ return 0.5f*x*(1.f+erff(x*0.70710678118654752f)); }
__device__ __forceinline__ float siluf(float x){ return x/(1.f+expf(-x)); }
__device__ __forceinline__ float sigmf(float x){ return 1.f/(1.f+expf(-x)); }

// ---------------- pack conv weights [o][i][3] -> float4[i*64+o] ----------------
__global__ void k_pack(const float* __restrict__ c1, const float* __restrict__ c2,
                       const float* __restrict__ gw){
    int idx = blockIdx.x*256 + threadIdx.x;
    if (idx >= 11*4096) return;
    int slot = idx >> 12; int r = idx & 4095; int o = r >> 6; int i = r & 63;
    const float* src;
    if (slot < 4)      src = c1 + slot*12288;
    else if (slot < 8) src = c2 + (slot-4)*12288;
    else               src = gw + (slot-8)*12288;
    const float* w = src + (o*64 + i)*3;
    ((float4*)g_W4s)[slot*4096 + i*64 + o] = make_float4(w[0], w[1], w[2], 0.f);
}

// ---------------- stat: mean over L (one block per (b,c) row) ----------------
__global__ void k_stat(const float* __restrict__ src){
    int r = blockIdx.x;
    const float* p = src + (size_t)r*L;
    float s = 0.f;
    for (int i = threadIdx.x; i < L; i += 256) s += p[i];
    __shared__ float red[256];
    red[threadIdx.x] = s; __syncthreads();
    for (int o = 128; o > 0; o >>= 1){
        if (threadIdx.x < o) red[threadIdx.x] += red[threadIdx.x+o];
        __syncthreads();
    }
    if (threadIdx.x == 0) g_stat[r] = red[0]*(1.f/(float)L);
}

// ---------------- dywan MLP + ortho (single block) ----------------
__global__ void k_mlp(const float* __restrict__ w1, const float* __restrict__ b1,
                      const float* __restrict__ wg1, const float* __restrict__ bg1,
                      const float* __restrict__ wg2, const float* __restrict__ bg2){
    __shared__ float ss[512], h1[512], h2[1024], sf[112];
    int tid = threadIdx.x;
    for (int i = tid; i < 512; i += 256) ss[i] = g_stat[i];
    __syncthreads();
    for (int idx = tid; idx < 512; idx += 256){
        int b = idx >> 6, j = idx & 63;
        float s = b1[j];
        const float* w = w1 + j*64; const float* st = ss + b*64;
        #pragma unroll 8
        for (int c = 0; c < 64; c++) s += w[c]*st[c];
        h1[idx] = geluf(s);
    }
    __syncthreads();
    for (int idx = tid; idx < 1024; idx += 256){
        int b = idx >> 7, j = idx & 127;
        float s = bg1[j];
        const float* w = wg1 + j*64; const float* hh = h1 + b*64;
        #pragma unroll 8
        for (int c = 0; c < 64; c++) s += w[c]*hh[c];
        h2[idx] = geluf(s);
    }
    __syncthreads();
    if (tid < 112){
        int b = tid/14, j = tid%14;
        float s = bg2[j];
        const float* w = wg2 + j*128; const float* hh = h2 + b*128;
        #pragma unroll 8
        for (int c = 0; c < 128; c++) s += w[c]*hh[c];
        sf[b*14+j] = s;
        if (j < 7) g_lo[b*7+j] = s; else g_hi[b*7+(j-7)] = s;
    }
    __syncthreads();
    if (tid == 0){
        float sm = 0.f;
        for (int b = 0; b < 8; b++){
            float prev = 0.f;
            for (int i = 0; i < 7; i++){ float v = sf[b*14+i]; sm += fabsf(v-prev); prev = v; }
            sm += fabsf(prev);
        }
        float lo_smooth = sm/64.f;
        float lon[8][7];
        for (int b = 0; b < 8; b++){
            float n = 0.f;
            for (int i = 0; i < 7; i++){ float v = sf[b*14+i]; n += v*v; }
            n = sqrtf(n) + 1e-8f;
            for (int i = 0; i < 7; i++) lon[b][i] = sf[b*14+i]/n;
        }
        float shift = 0.f;
        for (int s = 1; s <= 3; s++){
            float t = 0.f;
            for (int b = 0; b < 8; b++)
                for (int i = 0; i < 7; i++)
                    for (int jj = 0; jj < 7; jj++)
                        t += fabsf(lon[b][i]*lon[b][(jj - s + 7)%7]);
            shift += t/(8.f*49.f);
        }
        float amp = 0.f;
        for (int b = 0; b < 8; b++){
            float q = 0.f;
            for (int i = 0; i < 7; i++) q += lon[b][i]*lon[b][i];
            amp += fabsf(q - 1.f);
        }
        amp /= 8.f;
        g_ortho[0] = 0.01f*(shift+amp) + 0.1f*lo_smooth;
    }
}

// ---------------- per-batch 7-tap filter (edge pad), both filters ----------------
__global__ void k_filt(const float* __restrict__ src, float* __restrict__ na,
                       float* __restrict__ det){
    int idx = blockIdx.x*256 + threadIdx.x;
    if (idx >= BCL) return;
    int l = idx & (L-1);
    int bc = idx >> 11;
    int b = bc >> 6;
    const float* p = src + (size_t)bc*L;
    const float* flo = g_lo + b*7; const float* fhi = g_hi + b*7;
    float sa = 0.f, sd = 0.f;
    #pragma unroll
    for (int t = 0; t < 7; t++){
        int m = l + t - 3; m = m < 0 ? 0 : (m > L-1 ? L-1 : m);
        float v = p[m];
        sa += v*flo[t]; sd += v*fhi[t];
    }
    na[idx] = sa; det[idx] = sd;
}

__global__ void k_copy4(const float4* __restrict__ s, float4* __restrict__ d){
    int i = blockIdx.x*256 + threadIdx.x;
    if (i < BCL/4) d[i] = s[i];
}

__global__ void k_init(){
    if (threadIdx.x == 0){ g_mm[0] = 0x7f7fffffu; g_mm[1] = 0u; }
}

// ---------------- adaptive time grid pass 1: per-row partial sums + min/max ----------------
__global__ void k_grid1(const float* __restrict__ c){
    __shared__ float sd[2048];
    __shared__ float R[6][256];
    int r = blockIdx.x;
    const float* p = c + (size_t)r*2048;
    int t = threadIdx.x;
    for (int i = t; i < 2048; i += 256) sd[i] = p[i];
    __syncthreads();
    float s1=0.f,s2=0.f,s3=0.f,s4=0.f, mn=3.4e38f, mx=0.f;
    for (int jj = t; jj < 2047; jj += 256){
        int lo = jj-2; if (lo < 0) lo = 0;
        int hi = jj+2; if (hi > 2046) hi = 2046;
        float g = 0.f;
        for (int q = lo; q <= hi; q++) g += fabsf(sd[q+1]-sd[q]);
        float inten = g*0.2f;
        mn = fminf(mn, inten); mx = fmaxf(mx, inten);
        if (jj < 511)  s1 += inten;
        if (jj < 1023) s2 += inten;
        if (jj < 1534) s3 += inten;
        if (jj < 2046) s4 += inten;
    }
    R[0][t]=s1; R[1][t]=s2; R[2][t]=s3; R[3][t]=s4; R[4][t]=mn; R[5][t]=mx;
    __syncthreads();
    for (int o = 128; o > 0; o >>= 1){
        if (t < o){
            R[0][t]+=R[0][t+o]; R[1][t]+=R[1][t+o]; R[2][t]+=R[2][t+o]; R[3][t]+=R[3][t+o];
            R[4][t]=fminf(R[4][t],R[4][t+o]); R[5][t]=fmaxf(R[5][t],R[5][t+o]);
        }
        __syncthreads();
    }
    if (t == 0){
        g_rows[r*4+0]=R[0][0]; g_rows[r*4+1]=R[1][0]; g_rows[r*4+2]=R[2][0]; g_rows[r*4+3]=R[3][0];
        atomicMin(&g_mm[0], __float_as_uint(R[4][0]));
        atomicMax(&g_mm[1], __float_as_uint(R[5][0]));
    }
}

// ---------------- grid pass 2: ts[0..4] ----------------
__global__ void k_grid2(){
    __shared__ float R[5][256];
    float mn = __uint_as_float(g_mm[0]);
    float mx = __uint_as_float(g_mm[1]);
    float a, bb;
    if (mx - mn < 1e-8f){ a = 0.f; bb = 0.5f; }
    else { a = 0.9f/(mx - mn + 1e-30f); bb = 0.1f - a*mn; }
    int t = threadIdx.x;
    float p1=0.f,p2=0.f,p3=0.f,p4=0.f,m=-1.f;
    for (int r = t; r < 512; r += 256){
        float t1 = a*g_rows[r*4+0] + bb*511.f;
        float t2 = a*g_rows[r*4+1] + bb*1023.f;
        float t3 = a*g_rows[r*4+2] + bb*1534.f;
        float t4 = a*g_rows[r*4+3] + bb*2046.f;
        p1+=t1; p2+=t2; p3+=t3; p4+=t4; m = fmaxf(m, t4);
    }
    R[0][t]=p1; R[1][t]=p2; R[2][t]=p3; R[3][t]=p4; R[4][t]=m;
    __syncthreads();
    for (int o = 128; o > 0; o >>= 1){
        if (t < o){
            R[0][t]+=R[0][t+o]; R[1][t]+=R[1][t+o]; R[2][t]+=R[2][t+o]; R[3][t]+=R[3][t+o];
            R[4][t]=fmaxf(R[4][t],R[4][t+o]);
        }
        __syncthreads();
    }
    if (t == 0){
        float M = fmaxf(R[4][0], 1e-12f);
        float inv = 1.f/(512.f*M);
        g_ts[0]=0.f; g_ts[1]=R[0][0]*inv; g_ts[2]=R[1][0]*inv; g_ts[3]=R[2][0]*inv; g_ts[4]=R[3][0]*inv;
    }
}

// ---------------- modulation table: [j][s][{1+g+se | beta}][64] ----------------
__global__ void k_mod(int lvl, const float* __restrict__ wt, const float* __restrict__ bt,
                      const float* __restrict__ wm, const float* __restrict__ bm,
                      const float* __restrict__ emb){
    int idx = blockIdx.x*256 + threadIdx.x;   // 2048
    if (idx >= 2048) return;
    int js = idx >> 7; int r = idx & 127;
    int j = js >> 2, s = js & 3;
    float t0 = g_ts[j], t1 = g_ts[j+1];
    float t = (s == 0) ? t0 : (s == 3 ? t1 : t0 + 0.5f*(t1-t0));
    float acc = bm[lvl*128 + r];
    #pragma unroll
    for (int k = 0; k < 16; k++){
        float te = siluf(wt[lvl*16+k]*t + bt[lvl*16+k]);
        acc = fmaf(wm[(lvl*128+r)*16+k], te, acc);
    }
    if (r < 64) g_modb[js*128 + r] = 1.f + acc + emb[(lvl*8+lvl)*64 + r];
    else        g_modb[js*128 + 64 + (r-64)] = acc;
}

// ---------------- energy: per-batch mean of squares ----------------
__global__ void k_energy(const float* __restrict__ src, int off){
    int b = blockIdx.x;
    const float* p = src + (size_t)b*131072;
    double s = 0.0;
    for (int i = threadIdx.x; i < 131072; i += 256){ float v = p[i]; s += (double)v*(double)v; }
    __shared__ double red[256];
    red[threadIdx.x] = s; __syncthreads();
    for (int o = 128; o > 0; o >>= 1){
        if (threadIdx.x < o) red[threadIdx.x] += red[threadIdx.x+o];
        __syncthreads();
    }
    if (threadIdx.x == 0) g_energy[off+b] = (float)(red[0]/131072.0);
}

__global__ void k_scale(const float4* __restrict__ y, float4* __restrict__ dst){
    int idx = blockIdx.x*256 + threadIdx.x;
    if (idx >= BCL/4) return;
    int b = idx >> 15;
    float sc = sqrtf(g_energy[b]/(g_energy[8+b]+1e-8f));
    float4 v = y[idx];
    v.x*=sc; v.y*=sc; v.z*=sc; v.w*=sc;
    dst[idx] = v;
}

// ---------------- core conv (C=64 -> 64, k=3, pad=1, zero pad) ----------------
// mode 0: dst = gelu(conv + bias)
// mode 1: RK4 stage epilogue (reads g_ts, g_modb)
// mode 2: gate: dst = cur + sigmoid(conv+bias)*det ; optional outdet = det
__global__ void __launch_bounds__(256,1)
k_conv(const float* __restrict__ src, const float4* __restrict__ W4,
       const float* __restrict__ bias, float* __restrict__ dst, int mode,
       const float* __restrict__ yin, const float* __restrict__ yv,
       float* __restrict__ acc, float* __restrict__ yinout, int j, int s,
       const float* __restrict__ det, float* __restrict__ outdet)
{
    __shared__ float xs[64*132];
    int b = blockIdx.y;
    int l0 = blockIdx.x*128;
    int tid = threadIdx.x;
    const float* sb = src + (size_t)b*64*2048;
    for (int idx = tid; idx < 64*132; idx += 256){
        int row = idx/132, p = idx - row*132;
        int gl = l0 + p - 1;
        float v = 0.f;
        if (p < 130 && gl >= 0 && gl < 2048) v = sb[row*2048 + gl];
        xs[idx] = v;
    }
    __syncthreads();
    int w = tid >> 5, lane = tid & 31;
    int o = ((w & 1) << 5) | lane;
    int lseg = (w >> 1) << 5;          // 0,32,64,96
    float a0[32];
    #pragma unroll
    for (int l = 0; l < 32; l++) a0[l] = 0.f;
    for (int i = 0; i < 64; i++){
        float4 wv = W4[i*64 + o];
        float xv[36];
        const float4* xp = (const float4*)(xs + i*132 + lseg);
        #pragma unroll
        for (int q = 0; q < 9; q++){
            float4 t4 = xp[q];
            xv[4*q]=t4.x; xv[4*q+1]=t4.y; xv[4*q+2]=t4.z; xv[4*q+3]=t4.w;
        }
        #pragma unroll
        for (int l = 0; l < 32; l++){
            a0[l] = fmaf(wv.x, xv[l],   a0[l]);
            a0[l] = fmaf(wv.y, xv[l+1], a0[l]);
            a0[l] = fmaf(wv.z, xv[l+2], a0[l]);
        }
    }
    float bo = bias[o];
    size_t obase = (size_t)b*64*2048 + (size_t)o*2048 + l0 + lseg;
    if (mode == 0){
        #pragma unroll 4
        for (int l = 0; l < 32; l++) dst[obase+l] = geluf(a0[l]+bo);
    } else if (mode == 1){
        float tsj = g_ts[j], dt = g_ts[j+1] - tsj;
        int msel = (j*4+s)*128;
        float m1p = g_modb[msel + o];
        float bet = g_modb[msel + 64 + o];
        float c_acc = (s == 0 || s == 3) ? dt*(1.f/6.f) : dt*(1.f/3.f);
        float c_y   = (s == 2) ? dt : dt*0.5f;
        #pragma unroll 4
        for (int l = 0; l < 32; l++){
            float hv = (a0[l]+bo)*m1p + bet;
            float kv = siluf(hv) - 0.1f*yin[obase+l];
            if (s == 0){
                float yvv = yv[obase+l];
                acc[obase+l] = yvv + c_acc*kv;
                yinout[obase+l] = yvv + c_y*kv;
            } else if (s < 3){
                acc[obase+l] += c_acc*kv;
                yinout[obase+l] = yv[obase+l] + c_y*kv;
            } else {
                yinout[obase+l] = acc[obase+l] + c_acc*kv;
            }
        }
    } else {
        #pragma unroll 4
        for (int l = 0; l < 32; l++){
            float g = sigmf(a0[l]+bo);
            float dv = det[obase+l];
            float cv = xs[o*132 + lseg + l + 1];
            dst[obase+l] = cv + g*dv;
            if (outdet) outdet[obase+l] = dv;
        }
    }
}

// ---------------- 1x1 attention (C->16->C) + detail modulation ----------------
__global__ void k_attn(const float* __restrict__ cur,
                       const float* __restrict__ w1, const float* __restrict__ b1,
                       const float* __restrict__ w2, const float* __restrict__ b2,
                       const float* __restrict__ det, float* __restrict__ dmod,
                       float* __restrict__ outdet){
    __shared__ float sm[128*65];
    int b = blockIdx.y, l0 = blockIdx.x*128;
    int tid = threadIdx.x;
    for (int idx = tid; idx < 64*128; idx += 128){
        int c = idx >> 7, l = idx & 127;
        sm[l*65 + c] = cur[((size_t)b*64+c)*2048 + l0 + l];
    }
    __syncthreads();
    int l = tid;
    float h16[16];
    #pragma unroll
    for (int k = 0; k < 16; k++){
        float a = b1[k];
        const float* wr = w1 + k*64;
        #pragma unroll 8
        for (int c = 0; c < 64; c++) a += wr[c]*sm[l*65+c];
        h16[k] = geluf(a);
    }
    for (int c = 0; c < 64; c++){
        float a = b2[c];
        const float* wr = w2 + c*16;
        #pragma unroll
        for (int k = 0; k < 16; k++) a += wr[k]*h16[k];
        a = sigmf(a);
        size_t id = ((size_t)b*64+c)*2048 + l0 + l;
        float dv = det[id]*(1.f + a);
        dmod[id] = dv;
        outdet[id] = dv;
    }
}

__global__ void k_tail(float* out){ out[NOUT] = g_ortho[0]; }

// ---------------- host ----------------
extern "C" void kernel_launch(void* const* d_in, const int* in_sizes, int n_in,
                              void* d_out, int out_size) {
    const float* x      = (const float*)d_in[0];
    const float* dy_w1  = (const float*)d_in[1];
    const float* dy_b1  = (const float*)d_in[2];
    const float* dy_wg1 = (const float*)d_in[3];
    const float* dy_bg1 = (const float*)d_in[4];
    const float* dy_wg2 = (const float*)d_in[5];
    const float* dy_bg2 = (const float*)d_in[6];
    const float* c1w    = (const float*)d_in[7];
    const float* c1b    = (const float*)d_in[8];
    const float* c2w    = (const float*)d_in[9];
    const float* c2b    = (const float*)d_in[10];
    const float* wt     = (const float*)d_in[11];
    const float* bt     = (const float*)d_in[12];
    const float* wm     = (const float*)d_in[13];
    const float* bm     = (const float*)d_in[14];
    const float* emb    = (const float*)d_in[15];
    const float* gate_w = (const float*)d_in[16];
    const float* gate_b = (const float*)d_in[17];
    const float* a1w    = (const float*)d_in[18];
    const float* a1b    = (const float*)d_in[19];
    const float* a2w    = (const float*)d_in[20];
    const float* a2b    = (const float*)d_in[21];
    float* out = (float*)d_out;

    void* pbig = nullptr; cudaGetSymbolAddress(&pbig, g_big);
    float* big = (float*)pbig;
    void* pw4 = nullptr; cudaGetSymbolAddress(&pw4, g_W4s);
    float4* W4 = (float4*)pw4;

    float* bufA = big + (size_t)S_BUFA*BCL;
    float* bufB = big + (size_t)S_BUFB*BCL;
    float* detb = big + (size_t)S_DET*BCL;
    float* yb   = big + (size_t)S_Y*BCL;
    float* yinb = big + (size_t)S_YIN*BCL;
    float* accb = big + (size_t)S_ACC*BCL;
    float* hb   = big + (size_t)S_H*BCL;
    float* evob = big + (size_t)S_EVO*BCL;
    float* curA = big + (size_t)S_CURA*BCL;
    float* curB = big + (size_t)S_CURB*BCL;
    float* dmod = big + (size_t)S_DMOD*BCL;

    k_pack<<<176,256>>>(c1w, c2w, gate_w);

    // ---- decomposition (3 levels) ----
    const float* aps[3] = { x, bufA, bufB };
    float* naps[3] = { bufA, bufB, bufA };
    for (int lev = 0; lev < 3; lev++){
        k_stat<<<512,256>>>(aps[lev]);
        k_mlp<<<1,256>>>(dy_w1, dy_b1, dy_wg1, dy_bg1, dy_wg2, dy_bg2);
        k_filt<<<4096,256>>>(aps[lev], naps[lev], detb + (size_t)lev*BCL);
    }
    // approx = bufA

    dim3 cgrid(16, 8);
    // ---- ODE evolution per level ----
    for (int lvl = 0; lvl < 4; lvl++){
        const float* c = (lvl == 0) ? bufA : detb + (size_t)(lvl-1)*BCL;
        k_init<<<1,32>>>();
        k_grid1<<<512,256>>>(c);
        k_grid2<<<1,256>>>();
        k_mod<<<8,256>>>(lvl, wt, bt, wm, bm, emb);
        k_energy<<<8,256>>>(c, 0);
        k_copy4<<<1024,256>>>((const float4*)c, (float4*)yb);
        for (int j = 0; j < 4; j++){
            for (int s = 0; s < 4; s++){
                const float* cin = (s == 0) ? yb : yinb;
                k_conv<<<cgrid,256>>>(cin, W4 + (size_t)lvl*4096, c1b + lvl*64, hb, 0,
                                      nullptr, nullptr, nullptr, nullptr, 0, 0, nullptr, nullptr);
                float* yout = (s == 3) ? yb : yinb;
                k_conv<<<cgrid,256>>>(hb, W4 + (size_t)(4+lvl)*4096, c2b + lvl*64, nullptr, 1,
                                      cin, yb, accb, yout, j, s, nullptr, nullptr);
            }
        }
        k_energy<<<8,256>>>(yb, 8);
        float* dstE = (lvl == 0) ? curA : evob + (size_t)(lvl-1)*BCL;
        k_scale<<<1024,256>>>((const float4*)yb, (float4*)dstE);
    }

    // ---- reconstruction ----
    // i=2: no attention; current: curA -> curB; detail (unmodified) -> out slot 3
    k_conv<<<cgrid,256>>>(curA, W4 + (size_t)10*4096, gate_b + 2*64, curB, 2,
                          nullptr, nullptr, nullptr, nullptr, 0, 0,
                          evob + (size_t)2*BCL, out + (size_t)3*BCL);
    // i=1: attention + gate; curB -> curA; modified detail -> out slot 2
    k_attn<<<cgrid,128>>>(curB, a1w + 1024, a1b + 16, a2w + 1024, a2b + 64,
                          evob + (size_t)1*BCL, dmod, out + (size_t)2*BCL);
    k_conv<<<cgrid,256>>>(curB, W4 + (size_t)9*4096, gate_b + 64, curA, 2,
                          nullptr, nullptr, nullptr, nullptr, 0, 0, dmod, nullptr);
    // i=0: attention + gate; curA -> out slot 0; modified detail -> out slot 1
    k_attn<<<cgrid,128>>>(curA, a1w, a1b, a2w, a2b,
                          evob, dmod, out + (size_t)1*BCL);
    k_conv<<<cgrid,256>>>(curA, W4 + (size_t)8*4096, gate_b, out, 2,
                          nullptr, nullptr, nullptr, nullptr, 0, 0, dmod, nullptr);

    if (out_size > NOUT) k_tail<<<1,1>>>(out);
}

// round 4
// speedup vs baseline: 3.0240x; 3.0240x over previous
#include <cuda_runtime.h>
#include <math.h>

#define B 8
#define C 64
#define L 2048
#define BCL (B*C*L)          // 1048576
#define NOUT (4*BCL)

// buffer slots in g_big
#define S_BUFA 0
#define S_BUFB 1
#define S_DET  2   // 3 buffers (lvl 1..3 coeffs; double as y state)
#define S_YIN  5   // 4
#define S_ACC  9   // 4
#define S_EVO  13  // 3
#define S_CURA 16
#define S_CURB 17
#define S_DMOD 18
#define NBUF   19

// ---------------- device scratch (no allocation) ----------------
__device__ float g_big[(size_t)NBUF*BCL];
__device__ float g_W4s[11*4096*4];    // packed conv weights (float4 per (i,o))
__device__ float g_stat[512];
__device__ float g_lo[56], g_hi[56];
__device__ float g_ortho[1];
__device__ float g_ts[24];            // [lvl][5]
__device__ float g_rows[4*2048];      // [lvl][512 rows x 4 partials]
__device__ float g_modb[4*16*128];    // [lvl][j*4+s][{1+g+se | beta}x64]
__device__ float g_energy[64];        // [0..31] in, [32..63] out
__device__ unsigned g_mm[8];          // [lvl][min,max]

typedef unsigned long long ull;

// ---------------- helpers ----------------
__device__ __forceinline__ float geluf(float x){ return 0.5f*x*(1.f+erff(x*0.70710678118654752f)); }
__device__ __forceinline__ float siluf(float x){ return x/(1.f+expf(-x)); }
__device__ __forceinline__ float sigmf(float x){ return 1.f/(1.f+expf(-x)); }

__device__ __forceinline__ ull pk2(float v){
    ull r; asm("mov.b64 %0,{%1,%1};" : "=l"(r) : "f"(v)); return r;
}
__device__ __forceinline__ void upk(ull v, float& lo, float& hi){
    asm("mov.b64 {%0,%1},%2;" : "=f"(lo), "=f"(hi) : "l"(v));
}
__device__ __forceinline__ ull fma2(ull a, ull b, ull c){
    ull d; asm("fma.rn.f32x2 %0,%1,%2,%3;" : "=l"(d) : "l"(a), "l"(b), "l"(c)); return d;
}

__device__ __forceinline__ size_t yboff(int lvl){
    return (lvl == 0) ? (size_t)S_BUFA*BCL : (size_t)(S_DET+lvl-1)*BCL;
}

// ---------------- pack conv weights [o][i][3] -> float4[i*64+o] ----------------
__global__ void k_pack(const float* __restrict__ c1, const float* __restrict__ c2,
                       const float* __restrict__ gw){
    int idx = blockIdx.x*256 + threadIdx.x;
    if (idx >= 11*4096) return;
    int slot = idx >> 12; int r = idx & 4095; int o = r >> 6; int i = r & 63;
    const float* src;
    if (slot < 4)      src = c1 + slot*12288;
    else if (slot < 8) src = c2 + (slot-4)*12288;
    else               src = gw + (slot-8)*12288;
    const float* w = src + (o*64 + i)*3;
    ((float4*)g_W4s)[slot*4096 + i*64 + o] = make_float4(w[0], w[1], w[2], 0.f);
}

// ---------------- stat: mean over L ----------------
__global__ void k_stat(const float* __restrict__ src){
    int r = blockIdx.x;
    const float* p = src + (size_t)r*L;
    float s = 0.f;
    for (int i = threadIdx.x; i < L; i += 256) s += p[i];
    __shared__ float red[256];
    red[threadIdx.x] = s; __syncthreads();
    for (int o = 128; o > 0; o >>= 1){
        if (threadIdx.x < o) red[threadIdx.x] += red[threadIdx.x+o];
        __syncthreads();
    }
    if (threadIdx.x == 0) g_stat[r] = red[0]*(1.f/(float)L);
}

// ---------------- dywan MLP + ortho (single block) ----------------
__global__ void k_mlp(const float* __restrict__ w1, const float* __restrict__ b1,
                      const float* __restrict__ wg1, const float* __restrict__ bg1,
                      const float* __restrict__ wg2, const float* __restrict__ bg2){
    __shared__ float ss[512], h1[512], h2[1024], sf[112];
    int tid = threadIdx.x;
    for (int i = tid; i < 512; i += 256) ss[i] = g_stat[i];
    __syncthreads();
    for (int idx = tid; idx < 512; idx += 256){
        int b = idx >> 6, j = idx & 63;
        float s = b1[j];
        const float* w = w1 + j*64; const float* st = ss + b*64;
        #pragma unroll 8
        for (int c = 0; c < 64; c++) s += w[c]*st[c];
        h1[idx] = geluf(s);
    }
    __syncthreads();
    for (int idx = tid; idx < 1024; idx += 256){
        int b = idx >> 7, j = idx & 127;
        float s = bg1[j];
        const float* w = wg1 + j*64; const float* hh = h1 + b*64;
        #pragma unroll 8
        for (int c = 0; c < 64; c++) s += w[c]*hh[c];
        h2[idx] = geluf(s);
    }
    __syncthreads();
    if (tid < 112){
        int b = tid/14, j = tid%14;
        float s = bg2[j];
        const float* w = wg2 + j*128; const float* hh = h2 + b*128;
        #pragma unroll 8
        for (int c = 0; c < 128; c++) s += w[c]*hh[c];
        sf[b*14+j] = s;
        if (j < 7) g_lo[b*7+j] = s; else g_hi[b*7+(j-7)] = s;
    }
    __syncthreads();
    if (tid == 0){
        float sm = 0.f;
        for (int b = 0; b < 8; b++){
            float prev = 0.f;
            for (int i = 0; i < 7; i++){ float v = sf[b*14+i]; sm += fabsf(v-prev); prev = v; }
            sm += fabsf(prev);
        }
        float lo_smooth = sm/64.f;
        float lon[8][7];
        for (int b = 0; b < 8; b++){
            float n = 0.f;
            for (int i = 0; i < 7; i++){ float v = sf[b*14+i]; n += v*v; }
            n = sqrtf(n) + 1e-8f;
            for (int i = 0; i < 7; i++) lon[b][i] = sf[b*14+i]/n;
        }
        float shift = 0.f;
        for (int s = 1; s <= 3; s++){
            float t = 0.f;
            for (int b = 0; b < 8; b++)
                for (int i = 0; i < 7; i++)
                    for (int jj = 0; jj < 7; jj++)
                        t += fabsf(lon[b][i]*lon[b][(jj - s + 7)%7]);
            shift += t/(8.f*49.f);
        }
        float amp = 0.f;
        for (int b = 0; b < 8; b++){
            float q = 0.f;
            for (int i = 0; i < 7; i++) q += lon[b][i]*lon[b][i];
            amp += fabsf(q - 1.f);
        }
        amp /= 8.f;
        g_ortho[0] = 0.01f*(shift+amp) + 0.1f*lo_smooth;
    }
}

// ---------------- per-batch 7-tap filter (edge pad), both filters ----------------
__global__ void k_filt(const float* __restrict__ src, float* __restrict__ na,
                       float* __restrict__ det){
    int idx = blockIdx.x*256 + threadIdx.x;
    if (idx >= BCL) return;
    int l = idx & (L-1);
    int bc = idx >> 11;
    int b = bc >> 6;
    const float* p = src + (size_t)bc*L;
    const float* flo = g_lo + b*7; const float* fhi = g_hi + b*7;
    float sa = 0.f, sd = 0.f;
    #pragma unroll
    for (int t = 0; t < 7; t++){
        int m = l + t - 3; m = m < 0 ? 0 : (m > L-1 ? L-1 : m);
        float v = p[m];
        sa += v*flo[t]; sd += v*fhi[t];
    }
    na[idx] = sa; det[idx] = sd;
}

__global__ void k_init(){
    int t = threadIdx.x;
    if (t < 4){ g_mm[t*2] = 0x7f7fffffu; g_mm[t*2+1] = 0u; }
}

// ---------------- adaptive time grid pass 1 (batched over 4 levels) ----------------
__global__ void k_grid1(){
    __shared__ float sd[2048];
    __shared__ float R[6][256];
    int lvl = blockIdx.x >> 9;
    int r = blockIdx.x & 511;
    const float* p = g_big + yboff(lvl) + (size_t)r*2048;
    int t = threadIdx.x;
    for (int i = t; i < 2048; i += 256) sd[i] = p[i];
    __syncthreads();
    float s1=0.f,s2=0.f,s3=0.f,s4=0.f, mn=3.4e38f, mx=0.f;
    for (int jj = t; jj < 2047; jj += 256){
        int lo = jj-2; if (lo < 0) lo = 0;
        int hi = jj+2; if (hi > 2046) hi = 2046;
        float g = 0.f;
        for (int q = lo; q <= hi; q++) g += fabsf(sd[q+1]-sd[q]);
        float inten = g*0.2f;
        mn = fminf(mn, inten); mx = fmaxf(mx, inten);
        if (jj < 511)  s1 += inten;
        if (jj < 1023) s2 += inten;
        if (jj < 1534) s3 += inten;
        if (jj < 2046) s4 += inten;
    }
    R[0][t]=s1; R[1][t]=s2; R[2][t]=s3; R[3][t]=s4; R[4][t]=mn; R[5][t]=mx;
    __syncthreads();
    for (int o = 128; o > 0; o >>= 1){
        if (t < o){
            R[0][t]+=R[0][t+o]; R[1][t]+=R[1][t+o]; R[2][t]+=R[2][t+o]; R[3][t]+=R[3][t+o];
            R[4][t]=fminf(R[4][t],R[4][t+o]); R[5][t]=fmaxf(R[5][t],R[5][t+o]);
        }
        __syncthreads();
    }
    if (t == 0){
        float* rows = g_rows + lvl*2048;
        rows[r*4+0]=R[0][0]; rows[r*4+1]=R[1][0]; rows[r*4+2]=R[2][0]; rows[r*4+3]=R[3][0];
        atomicMin(&g_mm[lvl*2+0], __float_as_uint(R[4][0]));
        atomicMax(&g_mm[lvl*2+1], __float_as_uint(R[5][0]));
    }
}

// ---------------- grid pass 2 (one block per level) ----------------
__global__ void k_grid2(){
    __shared__ float R[5][256];
    int lvl = blockIdx.x;
    float mn = __uint_as_float(g_mm[lvl*2+0]);
    float mx = __uint_as_float(g_mm[lvl*2+1]);
    float a, bb;
    if (mx - mn < 1e-8f){ a = 0.f; bb = 0.5f; }
    else { a = 0.9f/(mx - mn + 1e-30f); bb = 0.1f - a*mn; }
    int t = threadIdx.x;
    const float* rows = g_rows + lvl*2048;
    float p1=0.f,p2=0.f,p3=0.f,p4=0.f,m=-1.f;
    for (int r = t; r < 512; r += 256){
        float t1 = a*rows[r*4+0] + bb*511.f;
        float t2 = a*rows[r*4+1] + bb*1023.f;
        float t3 = a*rows[r*4+2] + bb*1534.f;
        float t4 = a*rows[r*4+3] + bb*2046.f;
        p1+=t1; p2+=t2; p3+=t3; p4+=t4; m = fmaxf(m, t4);
    }
    R[0][t]=p1; R[1][t]=p2; R[2][t]=p3; R[3][t]=p4; R[4][t]=m;
    __syncthreads();
    for (int o = 128; o > 0; o >>= 1){
        if (t < o){
            R[0][t]+=R[0][t+o]; R[1][t]+=R[1][t+o]; R[2][t]+=R[2][t+o]; R[3][t]+=R[3][t+o];
            R[4][t]=fmaxf(R[4][t],R[4][t+o]);
        }
        __syncthreads();
    }
    if (t == 0){
        float M = fmaxf(R[4][0], 1e-12f);
        float inv = 1.f/(512.f*M);
        float* ts = g_ts + lvl*5;
        ts[0]=0.f; ts[1]=R[0][0]*inv; ts[2]=R[1][0]*inv; ts[3]=R[2][0]*inv; ts[4]=R[3][0]*inv;
    }
}

// ---------------- modulation table (batched over levels) ----------------
__global__ void k_mod(const float* __restrict__ wt, const float* __restrict__ bt,
                      const float* __restrict__ wm, const float* __restrict__ bm,
                      const float* __restrict__ emb){
    int gid = blockIdx.x*256 + threadIdx.x;   // 4*2048
    if (gid >= 8192) return;
    int lvl = gid >> 11; int rem = gid & 2047;
    int js = rem >> 7; int r = rem & 127;
    int j = js >> 2, s = js & 3;
    float t0 = g_ts[lvl*5+j], t1 = g_ts[lvl*5+j+1];
    float t = (s == 0) ? t0 : (s == 3 ? t1 : t0 + 0.5f*(t1-t0));
    float acc = bm[lvl*128 + r];
    #pragma unroll
    for (int k = 0; k < 16; k++){
        float te = siluf(wt[lvl*16+k]*t + bt[lvl*16+k]);
        acc = fmaf(wm[(lvl*128+r)*16+k], te, acc);
    }
    if (r < 64) g_modb[(lvl*16+js)*128 + r] = 1.f + acc + emb[(lvl*8+lvl)*64 + r];
    else        g_modb[(lvl*16+js)*128 + 64 + (r-64)] = acc;
}

// ---------------- energy: per (lvl,b) mean of squares of y arrays ----------------
__global__ void k_energyB(int off){
    int lvl = blockIdx.x >> 3, b = blockIdx.x & 7;
    const float* p = g_big + yboff(lvl) + (size_t)b*131072;
    double s = 0.0;
    for (int i = threadIdx.x; i < 131072; i += 256){ float v = p[i]; s += (double)v*(double)v; }
    __shared__ double red[256];
    red[threadIdx.x] = s; __syncthreads();
    for (int o = 128; o > 0; o >>= 1){
        if (threadIdx.x < o) red[threadIdx.x] += red[threadIdx.x+o];
        __syncthreads();
    }
    if (threadIdx.x == 0) g_energy[off + lvl*8 + b] = (float)(red[0]/131072.0);
}

__global__ void k_scale(){
    int idx = blockIdx.x*256 + threadIdx.x;
    if (idx >= 4*(BCL/4)) return;
    int lvl = idx >> 18;
    int r = idx & (BCL/4 - 1);
    int b = r >> 15;
    float sc = sqrtf(g_energy[lvl*8+b]/(g_energy[32+lvl*8+b]+1e-8f));
    const float4* src = (const float4*)(g_big + yboff(lvl));
    float4* dst = (float4*)(g_big + ((lvl == 0) ? (size_t)S_CURA*BCL : (size_t)(S_EVO+lvl-1)*BCL));
    float4 v = src[r];
    v.x*=sc; v.y*=sc; v.z*=sc; v.w*=sc;
    dst[r] = v;
}

// ---------------- fused RK4 stage: conv1+gelu+conv2+mod+silu+RK4 update ----------------
// grid (32 ltiles, 8 batch, 4 levels), 256 threads, dynamic smem 75776B
__global__ void __launch_bounds__(256)
k_stage(const float* __restrict__ c1b, const float* __restrict__ c2b, int j, int s)
{
    extern __shared__ float smem[];
    float* xs  = smem;            // 64 x 76  (x, cols gl l0-3 .. l0+70; 74,75 pad 0)
    float* xso = smem + 4864;     // 64 x 76  (x shifted by +1 col)
    float* hs  = smem + 9728;     // 64 x 72  (h, cols ghl l0-2 .. l0+69)
    float* hso = smem + 14336;    // 64 x 72  (h shifted by +1 col)

    int lvl = blockIdx.z;
    int b   = blockIdx.y;
    int l0  = blockIdx.x*64;
    int tid = threadIdx.x;

    size_t ybo = yboff(lvl);
    size_t lvlbcl = (size_t)lvl*BCL;
    size_t cino = (s == 0) ? ybo : ((size_t)S_YIN*BCL + lvlbcl);
    const float* cin = g_big + cino + (size_t)b*64*2048;

    // load x tile
    for (int idx = tid; idx < 64*76; idx += 256){
        int row = idx/76, m = idx - row*76;
        int gl = l0 - 3 + m;
        float v = 0.f;
        if (m < 74 && gl >= 0 && gl < 2048) v = cin[row*2048 + gl];
        xs[idx] = v;
    }
    __syncthreads();
    // build shifted copy
    for (int idx = tid; idx < 64*76; idx += 256){
        int row = idx/76, m = idx - row*76;
        xso[idx] = (m < 75) ? xs[row*76 + m + 1] : 0.f;
    }
    __syncthreads();

    int o = tid & 63, seg = tid >> 6;
    const float4* W1 = ((const float4*)g_W4s) + (size_t)lvl*4096;
    const float4* W2 = ((const float4*)g_W4s) + (size_t)(4+lvl)*4096;

    // ---- phase 1: conv1 -> h (9 output pairs per thread, cols 2*(seg*9) .. +17) ----
    int pbase = seg*9;
    ull acc1[9];
    #pragma unroll
    for (int k = 0; k < 9; k++) acc1[k] = 0ull;
    for (int i = 0; i < 64; i++){
        float4 wv = W1[i*64 + o];
        ull w0 = pk2(wv.x), w1 = pk2(wv.y), w2 = pk2(wv.z);
        const ull* ep = (const ull*)(xs  + i*76) + pbase;
        const ull* op = (const ull*)(xso + i*76) + pbase;
        ull E[10], O[9];
        #pragma unroll
        for (int k = 0; k < 10; k++) E[k] = ep[k];
        #pragma unroll
        for (int k = 0; k < 9; k++)  O[k] = op[k];
        #pragma unroll
        for (int k = 0; k < 9; k++){
            acc1[k] = fma2(w0, E[k],   acc1[k]);
            acc1[k] = fma2(w1, O[k],   acc1[k]);
            acc1[k] = fma2(w2, E[k+1], acc1[k]);
        }
    }
    {
        float b1v = c1b[lvl*64 + o];
        #pragma unroll
        for (int k = 0; k < 9; k++){
            float lo, hi; upk(acc1[k], lo, hi);
            int p0 = 2*(pbase + k);
            int g0 = l0 - 2 + p0;
            float h0 = (g0 >= 0   && g0 < 2048)   ? geluf(lo + b1v) : 0.f;
            float h1 = (g0 >= -1  && g0 < 2047)   ? geluf(hi + b1v) : 0.f;
            hs[o*72 + p0]     = h0;
            hs[o*72 + p0 + 1] = h1;
        }
    }
    __syncthreads();
    for (int idx = tid; idx < 64*72; idx += 256){
        int row = idx/72, m = idx - row*72;
        hso[idx] = (m < 71) ? hs[row*72 + m + 1] : 0.f;
    }
    __syncthreads();

    // ---- phase 2: conv2 (8 output pairs per thread, out cols 2*(seg*8) .. +15) ----
    int jb = seg*8;
    ull acc2[8];
    #pragma unroll
    for (int k = 0; k < 8; k++) acc2[k] = 0ull;
    for (int i = 0; i < 64; i++){
        float4 wv = W2[i*64 + o];
        ull w0 = pk2(wv.x), w1 = pk2(wv.y), w2 = pk2(wv.z);
        const ull* hep = (const ull*)(hs  + i*72);
        const ull* hop = (const ull*)(hso + i*72);
        ull HO[9], HE[8];
        #pragma unroll
        for (int k = 0; k < 9; k++) HO[k] = hop[jb + k];
        #pragma unroll
        for (int k = 0; k < 8; k++) HE[k] = hep[jb + 1 + k];
        #pragma unroll
        for (int k = 0; k < 8; k++){
            acc2[k] = fma2(w0, HO[k],   acc2[k]);
            acc2[k] = fma2(w1, HE[k],   acc2[k]);
            acc2[k] = fma2(w2, HO[k+1], acc2[k]);
        }
    }

    // ---- epilogue: modulation + silu - 0.1*y -> kv, then coalesced RK4 ----
    float kvv[16];
    {
        float m1p = g_modb[(lvl*16 + j*4 + s)*128 + o];
        float bet = g_modb[(lvl*16 + j*4 + s)*128 + 64 + o];
        float b2v = c2b[lvl*64 + o];
        #pragma unroll
        for (int k = 0; k < 8; k++){
            float lo, hi; upk(acc2[k], lo, hi);
            int q0 = 2*(jb + k);
            float y0 = xs[o*76 + q0 + 3];
            float y1 = xs[o*76 + q0 + 4];
            kvv[2*k]   = siluf((lo + b2v)*m1p + bet) - 0.1f*y0;
            kvv[2*k+1] = siluf((hi + b2v)*m1p + bet) - 0.1f*y1;
        }
    }
    __syncthreads();
    #pragma unroll
    for (int k = 0; k < 16; k++) hs[o*72 + 2*jb + k] = kvv[k];
    __syncthreads();

    float tsj = g_ts[lvl*5 + j];
    float dt  = g_ts[lvl*5 + j + 1] - tsj;
    float c_acc = (s == 0 || s == 3) ? dt*(1.f/6.f) : dt*(1.f/3.f);
    float c_y   = (s == 2) ? dt : dt*0.5f;
    for (int idx = tid; idx < 4096; idx += 256){
        int o2 = idx >> 6, q = idx & 63;
        float kv = hs[o2*72 + q];
        size_t g = ((size_t)b*64 + o2)*2048 + l0 + q;
        if (s == 0){
            float yvv = g_big[ybo + g];
            g_big[(size_t)S_ACC*BCL + lvlbcl + g] = yvv + c_acc*kv;
            g_big[(size_t)S_YIN*BCL + lvlbcl + g] = yvv + c_y*kv;
        } else if (s < 3){
            float yvv = g_big[ybo + g];
            g_big[(size_t)S_ACC*BCL + lvlbcl + g] += c_acc*kv;
            g_big[(size_t)S_YIN*BCL + lvlbcl + g] = yvv + c_y*kv;
        } else {
            g_big[ybo + g] = g_big[(size_t)S_ACC*BCL + lvlbcl + g] + c_acc*kv;
        }
    }
}

// ---------------- recon conv (C=64 -> 64, k=3, pad=1) ----------------
// mode 0: dst = gelu(conv + bias)
// mode 2: gate: dst = cur + sigmoid(conv+bias)*det ; optional outdet = det
__global__ void __launch_bounds__(256,1)
k_conv(const float* __restrict__ src, const float4* __restrict__ W4,
       const float* __restrict__ bias, float* __restrict__ dst, int mode,
       const float* __restrict__ det, float* __restrict__ outdet)
{
    __shared__ float xs[64*132];
    int b = blockIdx.y;
    int l0 = blockIdx.x*128;
    int tid = threadIdx.x;
    const float* sb = src + (size_t)b*64*2048;
    for (int idx = tid; idx < 64*132; idx += 256){
        int row = idx/132, p = idx - row*132;
        int gl = l0 + p - 1;
        float v = 0.f;
        if (p < 130 && gl >= 0 && gl < 2048) v = sb[row*2048 + gl];
        xs[idx] = v;
    }
    __syncthreads();
    int w = tid >> 5, lane = tid & 31;
    int o = ((w & 1) << 5) | lane;
    int lseg = (w >> 1) << 5;
    float a0[32];
    #pragma unroll
    for (int l = 0; l < 32; l++) a0[l] = 0.f;
    for (int i = 0; i < 64; i++){
        float4 wv = W4[i*64 + o];
        float xv[36];
        const float4* xp = (const float4*)(xs + i*132 + lseg);
        #pragma unroll
        for (int q = 0; q < 9; q++){
            float4 t4 = xp[q];
            xv[4*q]=t4.x; xv[4*q+1]=t4.y; xv[4*q+2]=t4.z; xv[4*q+3]=t4.w;
        }
        #pragma unroll
        for (int l = 0; l < 32; l++){
            a0[l] = fmaf(wv.x, xv[l],   a0[l]);
            a0[l] = fmaf(wv.y, xv[l+1], a0[l]);
            a0[l] = fmaf(wv.z, xv[l+2], a0[l]);
        }
    }
    float bo = bias[o];
    size_t obase = (size_t)b*64*2048 + (size_t)o*2048 + l0 + lseg;
    if (mode == 0){
        #pragma unroll 4
        for (int l = 0; l < 32; l++) dst[obase+l] = geluf(a0[l]+bo);
    } else {
        #pragma unroll 4
        for (int l = 0; l < 32; l++){
            float g = sigmf(a0[l]+bo);
            float dv = det[obase+l];
            float cv = xs[o*132 + lseg + l + 1];
            dst[obase+l] = cv + g*dv;
            if (outdet) outdet[obase+l] = dv;
        }
    }
}

// ---------------- 1x1 attention (C->16->C) + detail modulation ----------------
__global__ void k_attn(const float* __restrict__ cur,
                       const float* __restrict__ w1, const float* __restrict__ b1,
                       const float* __restrict__ w2, const float* __restrict__ b2,
                       const float* __restrict__ det, float* __restrict__ dmod,
                       float* __restrict__ outdet){
    __shared__ float sm[128*65];
    int b = blockIdx.y, l0 = blockIdx.x*128;
    int tid = threadIdx.x;
    for (int idx = tid; idx < 64*128; idx += 128){
        int c = idx >> 7, l = idx & 127;
        sm[l*65 + c] = cur[((size_t)b*64+c)*2048 + l0 + l];
    }
    __syncthreads();
    int l = tid;
    float h16[16];
    #pragma unroll
    for (int k = 0; k < 16; k++){
        float a = b1[k];
        const float* wr = w1 + k*64;
        #pragma unroll 8
        for (int c = 0; c < 64; c++) a += wr[c]*sm[l*65+c];
        h16[k] = geluf(a);
    }
    for (int c = 0; c < 64; c++){
        float a = b2[c];
        const float* wr = w2 + c*16;
        #pragma unroll
        for (int k = 0; k < 16; k++) a += wr[k]*h16[k];
        a = sigmf(a);
        size_t id = ((size_t)b*64+c)*2048 + l0 + l;
        float dv = det[id]*(1.f + a);
        dmod[id] = dv;
        outdet[id] = dv;
    }
}

__global__ void k_tail(float* out){ out[NOUT] = g_ortho[0]; }

// ---------------- host ----------------
extern "C" void kernel_launch(void* const* d_in, const int* in_sizes, int n_in,
                              void* d_out, int out_size) {
    const float* x      = (const float*)d_in[0];
    const float* dy_w1  = (const float*)d_in[1];
    const float* dy_b1  = (const float*)d_in[2];
    const float* dy_wg1 = (const float*)d_in[3];
    const float* dy_bg1 = (const float*)d_in[4];
    const float* dy_wg2 = (const float*)d_in[5];
    const float* dy_bg2 = (const float*)d_in[6];
    const float* c1w    = (const float*)d_in[7];
    const float* c1b    = (const float*)d_in[8];
    const float* c2w    = (const float*)d_in[9];
    const float* c2b    = (const float*)d_in[10];
    const float* wt     = (const float*)d_in[11];
    const float* bt     = (const float*)d_in[12];
    const float* wm     = (const float*)d_in[13];
    const float* bm     = (const float*)d_in[14];
    const float* emb    = (const float*)d_in[15];
    const float* gate_w = (const float*)d_in[16];
    const float* gate_b = (const float*)d_in[17];
    const float* a1w    = (const float*)d_in[18];
    const float* a1b    = (const float*)d_in[19];
    const float* a2w    = (const float*)d_in[20];
    const float* a2b    = (const float*)d_in[21];
    float* out = (float*)d_out;

    static int smem_set = 0;
    if (!smem_set){
        cudaFuncSetAttribute(k_stage, cudaFuncAttributeMaxDynamicSharedMemorySize, 75776);
        smem_set = 1;
    }

    void* pbig = nullptr; cudaGetSymbolAddress(&pbig, g_big);
    float* big = (float*)pbig;
    void* pw4 = nullptr; cudaGetSymbolAddress(&pw4, g_W4s);
    float4* W4 = (float4*)pw4;

    float* bufA = big + (size_t)S_BUFA*BCL;
    float* bufB = big + (size_t)S_BUFB*BCL;
    float* detb = big + (size_t)S_DET*BCL;
    float* evob = big + (size_t)S_EVO*BCL;
    float* curA = big + (size_t)S_CURA*BCL;
    float* curB = big + (size_t)S_CURB*BCL;
    float* dmod = big + (size_t)S_DMOD*BCL;

    k_pack<<<176,256>>>(c1w, c2w, gate_w);

    // ---- decomposition (3 levels); final approx lands in bufA ----
    const float* aps[3] = { x, bufA, bufB };
    float* naps[3] = { bufA, bufB, bufA };
    for (int lev = 0; lev < 3; lev++){
        k_stat<<<512,256>>>(aps[lev]);
        k_mlp<<<1,256>>>(dy_w1, dy_b1, dy_wg1, dy_bg1, dy_wg2, dy_bg2);
        k_filt<<<4096,256>>>(aps[lev], naps[lev], detb + (size_t)lev*BCL);
    }

    // ---- ODE prep for all 4 levels ----
    k_init<<<1,32>>>();
    k_grid1<<<2048,256>>>();
    k_grid2<<<4,256>>>();
    k_mod<<<32,256>>>(wt, bt, wm, bm, emb);
    k_energyB<<<32,256>>>(0);

    // ---- RK4: 16 fused stages, all levels concurrently ----
    dim3 sgrid(32, 8, 4);
    for (int j = 0; j < 4; j++)
        for (int s = 0; s < 4; s++)
            k_stage<<<sgrid, 256, 75776>>>(c1b, c2b, j, s);

    k_energyB<<<32,256>>>(32);
    k_scale<<<4096,256>>>();

    // ---- reconstruction ----
    dim3 cgrid(16, 8);
    k_conv<<<cgrid,256>>>(curA, W4 + (size_t)10*4096, gate_b + 2*64, curB, 2,
                          evob + (size_t)2*BCL, out + (size_t)3*BCL);
    k_attn<<<cgrid,128>>>(curB, a1w + 1024, a1b + 16, a2w + 1024, a2b + 64,
                          evob + (size_t)1*BCL, dmod, out + (size_t)2*BCL);
    k_conv<<<cgrid,256>>>(curB, W4 + (size_t)9*4096, gate_b + 64, curA, 2,
                          dmod, nullptr);
    k_attn<<<cgrid,128>>>(curA, a1w, a1b, a2w, a2b,
                          evob, dmod, out + (size_t)1*BCL);
    k_conv<<<cgrid,256>>>(curA, W4 + (size_t)8*4096, gate_b, out, 2,
                          dmod, nullptr);

    if (out_size > NOUT) k_tail<<<1,1>>>(out);
}